// round 2
// baseline (speedup 1.0000x reference)
#include <cuda_runtime.h>
#include <math.h>

// Problem constants
#define BB 2
#define CIN 64
#define COUT 96
#define TT 8
#define HH 48
#define WW 48
#define NN (TT*HH*WW)        // 18432
#define K27 27
#define CK (CIN*K27)         // 1728
#define OFFC (3*K27)         // 81
#define PP 4                 // positions per block (48 % 4 == 0 -> row aligned)

// Scratch (static device memory; no allocation allowed)
__device__ float g_wt_off[CK*OFFC];            // [ck][81]
__device__ float g_wt[CK*COUT];                // [ck][96]
__device__ float g_doff[3][BB*K27*NN];         // dt, dy, dx : [b][k][n]
__device__ float g_scale[COUT];
__device__ float g_bias[COUT];

// ---------------------------------------------------------------------------
// Kernel 0: transpose weights  w[o][ck] -> wt[ck][o]
// ---------------------------------------------------------------------------
__global__ void prep_kernel(const float* __restrict__ w_off,
                            const float* __restrict__ w) {
    int i = blockIdx.x * blockDim.x + threadIdx.x;
    if (i < OFFC * CK) {
        int o = i / CK, ck = i % CK;
        g_wt_off[ck * OFFC + o] = w_off[i];
    }
    if (i < COUT * CK) {
        int o = i / CK, ck = i % CK;
        g_wt[ck * COUT + o] = w[i];
    }
}

// ---------------------------------------------------------------------------
// Kernel 1: offset conv (dense 3x3x3, 81 out-ch) -> tanh-scaled dt/dy/dx
// Block: 128 threads, handles 4 consecutive x positions of one (b,t,y) row.
// ---------------------------------------------------------------------------
__global__ void __launch_bounds__(128)
offset_conv_kernel(const float* __restrict__ x, const float* __restrict__ b_off) {
    const int groupsPerB = NN / PP;              // 4608
    int blk = blockIdx.x;
    int b = blk / groupsPerB;
    int g = blk - b * groupsPerB;
    int n_base = g * PP;
    int t  = n_base / (HH * WW);
    int y  = (n_base / WW) % HH;
    int x0 = n_base % WW;

    __shared__ __align__(16) float s[CK * PP];   // s[ck][p]
    int tid = threadIdx.x;

    // Stage A: integer-neighborhood gather
    if (tid < PP * K27) {
        int p = tid / K27, k = tid - p * K27;
        int kt = k / 9, ky = (k / 3) % 3, kx = k % 3;
        int zt = t + kt - 1, zy = y + ky - 1, zx = x0 + p + kx - 1;
        bool valid = (zt >= 0 && zt < TT && zy >= 0 && zy < HH && zx >= 0 && zx < WW);
        int base = valid ? ((zt * HH + zy) * WW + zx) : 0;
        const float* xp = x + (size_t)b * CIN * NN + base;
        float* sp = s + k * PP + p;              // stride K27*PP between c's
        #pragma unroll 4
        for (int c = 0; c < CIN; c++) {
            sp[c * (K27 * PP)] = valid ? xp[c * NN] : 0.0f;
        }
    }
    __syncthreads();

    // Stage B: 81 output channels, 4 positions each
    if (tid < OFFC) {
        float a0 = 0.f, a1 = 0.f, a2 = 0.f, a3 = 0.f;
        const float* wp = g_wt_off + tid;
        const float4* s4 = (const float4*)s;
        #pragma unroll 8
        for (int ck = 0; ck < CK; ck++) {
            float wv = wp[ck * OFFC];
            float4 sv = s4[ck];
            a0 = fmaf(wv, sv.x, a0);
            a1 = fmaf(wv, sv.y, a1);
            a2 = fmaf(wv, sv.z, a2);
            a3 = fmaf(wv, sv.w, a3);
        }
        float bo = b_off[tid];
        int axis = tid / K27, k = tid - axis * K27;
        float sc = (axis == 0) ? 1.0f : 2.0f;   // MAX_T / MAX_XY
        float* dst = &g_doff[axis][(size_t)(b * K27 + k) * NN + n_base];
        dst[0] = tanhf(a0 + bo) * sc;
        dst[1] = tanhf(a1 + bo) * sc;
        dst[2] = tanhf(a2 + bo) * sc;
        dst[3] = tanhf(a3 + bo) * sc;
    }
}

// ---------------------------------------------------------------------------
// Kernel 2: deformable conv (trilinear sample + [96 x 1728] matvec per pos)
// Writes pre-BN output into d_out.
// ---------------------------------------------------------------------------
__global__ void __launch_bounds__(128)
deform_conv_kernel(const float* __restrict__ x, float* __restrict__ out) {
    const int groupsPerB = NN / PP;
    int blk = blockIdx.x;
    int b = blk / groupsPerB;
    int g = blk - b * groupsPerB;
    int n_base = g * PP;
    int t  = n_base / (HH * WW);
    int y  = (n_base / WW) % HH;
    int x0 = n_base % WW;

    __shared__ __align__(16) float s[CK * PP];   // s[ck][p]
    int tid = threadIdx.x;

    // Stage A: trilinear gather (one thread per (p,k))
    if (tid < PP * K27) {
        int p = tid / K27, k = tid - p * K27;
        int n = n_base + p;
        int kt = k / 9, ky = (k / 3) % 3, kx = k % 3;
        size_t oidx = (size_t)(b * K27 + k) * NN + n;
        float dt = g_doff[0][oidx];
        float dy = g_doff[1][oidx];
        float dx = g_doff[2][oidx];
        float pt = (float)(t + kt - 1) + dt;
        float py = (float)(y + ky - 1) + dy;
        float px = (float)(x0 + p + kx - 1) + dx;
        float tf = floorf(pt), yf = floorf(py), xf = floorf(px);
        int it = (int)tf, iy = (int)yf, ix = (int)xf;
        float ft = pt - tf, fy = py - yf, fx = px - xf;

        int   idx8[8];
        float w8[8];
        #pragma unroll
        for (int j = 0; j < 8; j++) {
            int at = (j >> 2) & 1, ay = (j >> 1) & 1, ax = j & 1;
            int ti = it + at, yi = iy + ay, xi = ix + ax;
            bool valid = (ti >= 0 && ti < TT && yi >= 0 && yi < HH &&
                          xi >= 0 && xi < WW);
            float wv = (at ? ft : 1.0f - ft) * (ay ? fy : 1.0f - fy)
                     * (ax ? fx : 1.0f - fx);
            w8[j]   = valid ? wv : 0.0f;
            idx8[j] = valid ? (ti * HH + yi) * WW + xi : 0;
        }
        const float* xb = x + (size_t)b * CIN * NN;
        float* sp = s + k * PP + p;
        #pragma unroll 2
        for (int c = 0; c < CIN; c++) {
            const float* xc = xb + c * NN;
            float v = 0.0f;
            #pragma unroll
            for (int j = 0; j < 8; j++) v = fmaf(w8[j], xc[idx8[j]], v);
            sp[c * (K27 * PP)] = v;
        }
    }
    __syncthreads();

    // Stage B: 96 output channels x 4 positions
    if (tid < COUT) {
        float a0 = 0.f, a1 = 0.f, a2 = 0.f, a3 = 0.f;
        const float* wp = g_wt + tid;
        const float4* s4 = (const float4*)s;
        #pragma unroll 8
        for (int ck = 0; ck < CK; ck++) {
            float wv = wp[ck * COUT];
            float4 sv = s4[ck];
            a0 = fmaf(wv, sv.x, a0);
            a1 = fmaf(wv, sv.y, a1);
            a2 = fmaf(wv, sv.z, a2);
            a3 = fmaf(wv, sv.w, a3);
        }
        size_t ob = (size_t)(b * COUT + tid) * NN + n_base;
        out[ob + 0] = a0;
        out[ob + 1] = a1;
        out[ob + 2] = a2;
        out[ob + 3] = a3;
    }
}

// ---------------------------------------------------------------------------
// Kernel 3: per-channel batch stats -> scale/bias (one block per channel)
// ---------------------------------------------------------------------------
__global__ void __launch_bounds__(256)
bn_stats_kernel(const float* __restrict__ out,
                const float* __restrict__ gamma,
                const float* __restrict__ beta) {
    int c = blockIdx.x;
    int tid = threadIdx.x;
    double sum = 0.0, sq = 0.0;
    for (int i = tid; i < BB * NN; i += 256) {
        int b = (i >= NN) ? 1 : 0;
        int n = i - b * NN;
        float v = out[(size_t)(b * COUT + c) * NN + n];
        sum += v;
        sq  += (double)v * v;
    }
    __shared__ double ssum[256];
    __shared__ double ssq[256];
    ssum[tid] = sum; ssq[tid] = sq;
    __syncthreads();
    for (int off = 128; off > 0; off >>= 1) {
        if (tid < off) {
            ssum[tid] += ssum[tid + off];
            ssq[tid]  += ssq[tid + off];
        }
        __syncthreads();
    }
    if (tid == 0) {
        double cnt = (double)(BB * NN);
        double mean = ssum[0] / cnt;
        double var  = ssq[0] / cnt - mean * mean;
        float inv = (float)(1.0 / sqrt(var + 1e-5));
        float sc = gamma[c] * inv;
        g_scale[c] = sc;
        g_bias[c]  = beta[c] - (float)mean * sc;
    }
}

// ---------------------------------------------------------------------------
// Kernel 4: BN apply + ReLU (in place on d_out)
// ---------------------------------------------------------------------------
__global__ void __launch_bounds__(512)
bn_apply_kernel(float* __restrict__ out) {
    int i = blockIdx.x * blockDim.x + threadIdx.x;
    if (i < BB * COUT * NN) {
        int c = (i / NN) % COUT;
        float v = fmaf(out[i], g_scale[c], g_bias[c]);
        out[i] = fmaxf(v, 0.0f);
    }
}

// ---------------------------------------------------------------------------
extern "C" void kernel_launch(void* const* d_in, const int* in_sizes, int n_in,
                              void* d_out, int out_size) {
    const float* x     = (const float*)d_in[0];
    const float* w_off = (const float*)d_in[1];
    const float* b_off = (const float*)d_in[2];
    const float* w     = (const float*)d_in[3];
    const float* gamma = (const float*)d_in[4];
    const float* beta  = (const float*)d_in[5];
    float* out = (float*)d_out;

    int prep_total = COUT * CK;  // 165888 (covers 81*CK too)
    prep_kernel<<<(prep_total + 255) / 256, 256>>>(w_off, w);

    int blocks = BB * NN / PP;   // 9216
    offset_conv_kernel<<<blocks, 128>>>(x, b_off);
    deform_conv_kernel<<<blocks, 128>>>(x, out);

    bn_stats_kernel<<<COUT, 256>>>(out, gamma, beta);

    int total = BB * COUT * NN;  // 3538944
    bn_apply_kernel<<<(total + 511) / 512, 512>>>(out);
}

// round 5
// speedup vs baseline: 4.4876x; 4.4876x over previous
#include <cuda_runtime.h>
#include <math.h>
#include <stdint.h>

// ---------------------------------------------------------------------------
// Problem constants
// ---------------------------------------------------------------------------
#define BB 2
#define CIN 64
#define COUT 96
#define TT 8
#define HH 48
#define WW 48
#define NN (TT*HH*WW)          // 18432
#define K27 27
#define CK (CIN*K27)           // 1728  (kk = k*64 + c ordering)
#define OFFC (3*K27)           // 81
#define BN_TOT (BB*NN)         // 36864
#define NTILE 128
#define NTILES (BN_TOT/NTILE)  // 288
#define KC 32                  // K per smem chunk (floats)
#define NCHUNK (CK/KC)         // 54

// ---------------------------------------------------------------------------
// Static device scratch
// ---------------------------------------------------------------------------
__device__ float g_xT[(size_t)BB * NN * CIN];     // x transposed: [b][n][c]
__device__ float g_cols[(size_t)BN_TOT * CK];     // im2col [bn][k*64+c] ~255MB
__device__ float g_wt_off_pad[96 * CK];           // offset weights, padded+reordered
__device__ float g_wt[96 * CK];                   // conv weights, reordered
__device__ float g_doff[3][(size_t)BB * K27 * NN];
__device__ float g_sum[COUT], g_sqsum[COUT];
__device__ float g_scale[COUT], g_bias[COUT];

// ---------------------------------------------------------------------------
// Helpers
// ---------------------------------------------------------------------------
__device__ __forceinline__ float to_tf32(float x) {
    uint32_t r;
    asm("cvt.rna.tf32.f32 %0, %1;" : "=r"(r) : "f"(x));
    return __uint_as_float(r);
}

__device__ __forceinline__ float4 to_tf32_4(float4 v) {
    v.x = to_tf32(v.x); v.y = to_tf32(v.y);
    v.z = to_tf32(v.z); v.w = to_tf32(v.w);
    return v;
}

// mma.sync m16n8k8 tf32 (sm_80+ portable; runs on sm_103 tensor pipe)
__device__ __forceinline__ void mma_tf32(float d[4],
                                         uint32_t a0, uint32_t a1,
                                         uint32_t a2, uint32_t a3,
                                         uint32_t b0, uint32_t b1) {
    asm volatile(
        "mma.sync.aligned.m16n8k8.row.col.f32.tf32.tf32.f32 "
        "{%0,%1,%2,%3}, {%4,%5,%6,%7}, {%8,%9}, {%0,%1,%2,%3};"
        : "+f"(d[0]), "+f"(d[1]), "+f"(d[2]), "+f"(d[3])
        : "r"(a0), "r"(a1), "r"(a2), "r"(a3), "r"(b0), "r"(b1));
}

// ---------------------------------------------------------------------------
// Kernel: transpose x [b][c][n] -> g_xT [b][n][c]
// ---------------------------------------------------------------------------
__global__ void __launch_bounds__(256)
transpose_kernel(const float* __restrict__ x) {
    __shared__ float tile[64][33];
    int n0g = blockIdx.x * 32;
    int b = n0g >= NN;
    int nn = n0g - b * NN;
    int tx = threadIdx.x, ty = threadIdx.y;   // 32 x 8
    const float* xb = x + (size_t)b * CIN * NN;
    #pragma unroll
    for (int cc = 0; cc < 8; cc++) {
        int c = cc * 8 + ty;
        tile[c][tx] = xb[(size_t)c * NN + nn + tx];
    }
    __syncthreads();
    float* dst = g_xT + ((size_t)b * NN + nn) * CIN;
    #pragma unroll
    for (int q = 0; q < 4; q++) {
        int p = ty * 4 + q;
        dst[(size_t)p * CIN + tx]      = tile[tx][p];
        dst[(size_t)p * CIN + tx + 32] = tile[tx + 32][p];
    }
}

// ---------------------------------------------------------------------------
// Kernel: prep — reorder weights [o][c*27+k] -> [o][k*64+c], tf32-round, pad.
// ---------------------------------------------------------------------------
__global__ void prep_kernel(const float* __restrict__ w_off,
                            const float* __restrict__ w) {
    int i = blockIdx.x * blockDim.x + threadIdx.x;
    if (i < 96 * CK) {
        int o = i / CK, kk = i - o * CK;
        int k = kk >> 6, c = kk & 63;
        int src = c * K27 + k;
        g_wt[i] = to_tf32(w[o * CK + src]);
        g_wt_off_pad[i] = (o < OFFC) ? to_tf32(w_off[o * CK + src]) : 0.0f;
    }
    if (i < COUT) { g_sum[i] = 0.0f; g_sqsum[i] = 0.0f; }
}

// ---------------------------------------------------------------------------
// Kernel: dense im2col gather (offset conv).  cols[bn][k*64+c] = x shifted.
// ---------------------------------------------------------------------------
__global__ void __launch_bounds__(128)
dense_gather_kernel() {
    int bn = blockIdx.x;
    int b = bn >= NN;
    int n = bn - b * NN;
    int t = n / (HH * WW);
    int y = (n / WW) % HH;
    int xx = n % WW;

    __shared__ int s_didx[K27];
    int tid = threadIdx.x;
    if (tid < K27) {
        int k = tid;
        int kt = k / 9, ky = (k / 3) % 3, kx = k % 3;
        int zt = t + kt - 1, zy = y + ky - 1, zx = xx + kx - 1;
        bool valid = (zt >= 0 && zt < TT && zy >= 0 && zy < HH &&
                      zx >= 0 && zx < WW);
        s_didx[k] = valid ? (zt * HH + zy) * WW + zx : -1;
    }
    __syncthreads();

    const float4* xb4 = (const float4*)(g_xT + (size_t)b * NN * CIN);
    float4* dst = (float4*)(g_cols + (size_t)bn * CK);
    #pragma unroll
    for (int i = 0; i < 4; i++) {
        int u = tid + i * 128;
        if (u < K27 * 16) {
            int k = u >> 4, c4 = u & 15;
            int idx = s_didx[k];
            float4 v = make_float4(0.f, 0.f, 0.f, 0.f);
            if (idx >= 0) v = to_tf32_4(__ldg(xb4 + (size_t)idx * 16 + c4));
            dst[k * 16 + c4] = v;
        }
    }
}

// ---------------------------------------------------------------------------
// Kernel: deformable (trilinear) im2col gather from g_xT
// ---------------------------------------------------------------------------
__global__ void __launch_bounds__(128)
deform_gather_kernel() {
    int bn = blockIdx.x;
    int b = bn >= NN;
    int n = bn - b * NN;
    int t = n / (HH * WW);
    int y = (n / WW) % HH;
    int xx = n % WW;

    __shared__ int   s_idx[K27][8];
    __shared__ float s_w[K27][8];

    int tid = threadIdx.x;
    if (tid < K27) {
        int k = tid;
        int kt = k / 9, ky = (k / 3) % 3, kx = k % 3;
        size_t oidx = (size_t)(b * K27 + k) * NN + n;
        float pt = (float)(t + kt - 1) + g_doff[0][oidx];
        float py = (float)(y + ky - 1) + g_doff[1][oidx];
        float px = (float)(xx + kx - 1) + g_doff[2][oidx];
        float tf = floorf(pt), yf = floorf(py), xf = floorf(px);
        int it = (int)tf, iy = (int)yf, ix = (int)xf;
        float ft = pt - tf, fy = py - yf, fx = px - xf;
        #pragma unroll
        for (int j = 0; j < 8; j++) {
            int at = (j >> 2) & 1, ay = (j >> 1) & 1, ax = j & 1;
            int ti = it + at, yi = iy + ay, xi = ix + ax;
            bool valid = (ti >= 0 && ti < TT && yi >= 0 && yi < HH &&
                          xi >= 0 && xi < WW);
            float wv = (at ? ft : 1.0f - ft) * (ay ? fy : 1.0f - fy)
                     * (ax ? fx : 1.0f - fx);
            s_w[k][j]   = valid ? wv : 0.0f;
            s_idx[k][j] = valid ? (ti * HH + yi) * WW + xi : 0;
        }
    }
    __syncthreads();

    const float4* xb4 = (const float4*)(g_xT + (size_t)b * NN * CIN);
    float4* dst = (float4*)(g_cols + (size_t)bn * CK);
    #pragma unroll
    for (int i = 0; i < 4; i++) {
        int u = tid + i * 128;
        if (u < K27 * 16) {
            int k = u >> 4, c4 = u & 15;
            float4 acc = make_float4(0.f, 0.f, 0.f, 0.f);
            #pragma unroll
            for (int j = 0; j < 8; j++) {
                float wv = s_w[k][j];
                float4 v = __ldg(xb4 + (size_t)s_idx[k][j] * 16 + c4);
                acc.x = fmaf(wv, v.x, acc.x);
                acc.y = fmaf(wv, v.y, acc.y);
                acc.z = fmaf(wv, v.z, acc.z);
                acc.w = fmaf(wv, v.w, acc.w);
            }
            dst[k * 16 + c4] = to_tf32_4(acc);
        }
    }
}

// ---------------------------------------------------------------------------
// GEMM: C[128 pos x 96 ch] per CTA, K=1728, tf32 mma.sync.
// 256 threads = 8 warps in 2(M) x 4(N); warp tile 64 x 24.
// Smem k8-pair-permuted layout: element (row, c in 0..7) at
//   row*8 + (c&3)*2 + (c>>2)   -> fragment loads are single LDS.64.
// MODE 0: B = g_wt_off_pad, epilogue tanh -> g_doff
// MODE 1: B = g_wt,         epilogue -> out
// ---------------------------------------------------------------------------
#define SM_FLOATS (2*4096 + 2*3072)   // 14336 floats = 57344 B

template <int MODE>
__global__ void __launch_bounds__(256)
gemm_tf32_kernel(const float* __restrict__ b_off, float* __restrict__ out) {
    extern __shared__ float smem[];
    float* As = smem;            // [2][4][128][8]
    float* Bs = smem + 8192;     // [2][4][96][8]

    int tid = threadIdx.x;
    int wid = tid >> 5, lane = tid & 31;
    int gid = lane >> 2, tig = lane & 3;
    int warp_m = wid & 1, warp_n = wid >> 1;
    int n0 = blockIdx.x * NTILE;

    const float4* Amat = (const float4*)g_cols;
    const float4* Bmat = (const float4*)((MODE == 0) ? g_wt_off_pad : g_wt);

    // per-thread staging coordinates
    int arow = tid >> 3, ac4 = tid & 7;     // + i*32 rows (4 iters)
    // B: j = tid + i*256, row = j>>3, c4 = j&7  (3 iters, 768 total)

    float4 pa[4], pb[3];

    auto fetch = [&](int chunk) {
        #pragma unroll
        for (int i = 0; i < 4; i++)
            pa[i] = __ldg(Amat + (size_t)(n0 + arow + i * 32) * (CK / 4)
                          + chunk * 8 + ac4);
        #pragma unroll
        for (int i = 0; i < 3; i++) {
            int j = tid + i * 256;
            pb[i] = __ldg(Bmat + (size_t)(j >> 3) * (CK / 4)
                          + chunk * 8 + (j & 7));
        }
    };

    auto store_smem = [&](int buf) {
        // kk_local = c4*4 + e ; ks = c4>>1 ; pos = e*2 + (c4&1)
        #pragma unroll
        for (int i = 0; i < 4; i++) {
            float* p = As + buf * 4096 + (ac4 >> 1) * 1024
                     + (arow + i * 32) * 8 + (ac4 & 1);
            p[0] = pa[i].x; p[2] = pa[i].y; p[4] = pa[i].z; p[6] = pa[i].w;
        }
        #pragma unroll
        for (int i = 0; i < 3; i++) {
            int j = tid + i * 256;
            int row = j >> 3, c4 = j & 7;
            float* p = Bs + buf * 3072 + (c4 >> 1) * 768 + row * 8 + (c4 & 1);
            p[0] = pb[i].x; p[2] = pb[i].y; p[4] = pb[i].z; p[6] = pb[i].w;
        }
    };

    float d[4][3][4];
    #pragma unroll
    for (int mt = 0; mt < 4; mt++)
        #pragma unroll
        for (int nt = 0; nt < 3; nt++)
            #pragma unroll
            for (int q = 0; q < 4; q++) d[mt][nt][q] = 0.0f;

    fetch(0); store_smem(0); fetch(1);
    __syncthreads();

    for (int chunk = 0; chunk < NCHUNK; chunk++) {
        int buf = chunk & 1;
        const float2* Ap = (const float2*)(As + buf * 4096);
        const float2* Bp = (const float2*)(Bs + buf * 3072);
        #pragma unroll
        for (int ks = 0; ks < 4; ks++) {
            uint32_t af[4][4], bf[3][2];
            #pragma unroll
            for (int mt = 0; mt < 4; mt++) {
                int row = warp_m * 64 + mt * 16 + gid;
                float2 a02 = Ap[ks * 512 + row * 4 + tig];
                float2 a13 = Ap[ks * 512 + (row + 8) * 4 + tig];
                af[mt][0] = __float_as_uint(a02.x);
                af[mt][1] = __float_as_uint(a13.x);
                af[mt][2] = __float_as_uint(a02.y);
                af[mt][3] = __float_as_uint(a13.y);
            }
            #pragma unroll
            for (int nt = 0; nt < 3; nt++) {
                int col = warp_n * 24 + nt * 8 + gid;
                float2 b01 = Bp[ks * 384 + col * 4 + tig];
                bf[nt][0] = __float_as_uint(b01.x);
                bf[nt][1] = __float_as_uint(b01.y);
            }
            #pragma unroll
            for (int mt = 0; mt < 4; mt++)
                #pragma unroll
                for (int nt = 0; nt < 3; nt++)
                    mma_tf32(d[mt][nt], af[mt][0], af[mt][1], af[mt][2],
                             af[mt][3], bf[nt][0], bf[nt][1]);
        }
        if (chunk + 1 < NCHUNK) {
            store_smem((chunk + 1) & 1);
            if (chunk + 2 < NCHUNK) fetch(chunk + 2);
            __syncthreads();
        }
    }

    // epilogue
    #pragma unroll
    for (int mt = 0; mt < 4; mt++) {
        #pragma unroll
        for (int half = 0; half < 2; half++) {
            int row = warp_m * 64 + mt * 16 + gid + half * 8;
            int pos = n0 + row;
            int b = pos >= NN;
            int n = pos - b * NN;
            #pragma unroll
            for (int nt = 0; nt < 3; nt++) {
                #pragma unroll
                for (int e = 0; e < 2; e++) {
                    int col = warp_n * 24 + nt * 8 + tig * 2 + e;
                    float v = d[mt][nt][half * 2 + e];
                    if (MODE == 0) {
                        if (col < OFFC) {
                            int axis = col / K27, kk = col - axis * K27;
                            float sc = axis ? 2.0f : 1.0f;
                            float o = tanhf(v + __ldg(b_off + col)) * sc;
                            g_doff[axis][(size_t)(b * K27 + kk) * NN + n] = o;
                        }
                    } else {
                        out[(size_t)(b * COUT + col) * NN + n] = v;
                    }
                }
            }
        }
    }
}

// ---------------------------------------------------------------------------
// BN: parallel stats (atomic), finalize, apply
// ---------------------------------------------------------------------------
__global__ void __launch_bounds__(256)
bn_stats_kernel(const float* __restrict__ out) {
    int c = blockIdx.x >> 3;
    int slice = blockIdx.x & 7;
    const int SL = NN / 8;
    float s = 0.0f, q = 0.0f;
    for (int b = 0; b < BB; b++) {
        const float* p = out + (size_t)(b * COUT + c) * NN + slice * SL;
        for (int i = threadIdx.x; i < SL; i += 256) {
            float v = p[i];
            s += v; q += v * v;
        }
    }
    __shared__ float ss[256], sq[256];
    int tid = threadIdx.x;
    ss[tid] = s; sq[tid] = q;
    __syncthreads();
    for (int off = 128; off > 0; off >>= 1) {
        if (tid < off) { ss[tid] += ss[tid + off]; sq[tid] += sq[tid + off]; }
        __syncthreads();
    }
    if (tid == 0) {
        atomicAdd(&g_sum[c], ss[0]);
        atomicAdd(&g_sqsum[c], sq[0]);
    }
}

__global__ void bn_finalize_kernel(const float* __restrict__ gamma,
                                   const float* __restrict__ beta) {
    int c = threadIdx.x;
    if (c < COUT) {
        float cnt = (float)(BB * NN);
        float mean = g_sum[c] / cnt;
        float var = g_sqsum[c] / cnt - mean * mean;
        float inv = rsqrtf(var + 1e-5f);
        float sc = gamma[c] * inv;
        g_scale[c] = sc;
        g_bias[c] = beta[c] - mean * sc;
    }
}

__global__ void __launch_bounds__(256)
bn_apply_kernel(float* __restrict__ out) {
    int i4 = blockIdx.x * blockDim.x + threadIdx.x;
    const int TOT4 = BB * COUT * NN / 4;
    if (i4 < TOT4) {
        int c = (i4 / (NN / 4)) % COUT;
        float sc = g_scale[c], bi = g_bias[c];
        float4 v = reinterpret_cast<float4*>(out)[i4];
        v.x = fmaxf(fmaf(v.x, sc, bi), 0.0f);
        v.y = fmaxf(fmaf(v.y, sc, bi), 0.0f);
        v.z = fmaxf(fmaf(v.z, sc, bi), 0.0f);
        v.w = fmaxf(fmaf(v.w, sc, bi), 0.0f);
        reinterpret_cast<float4*>(out)[i4] = v;
    }
}

// ---------------------------------------------------------------------------
extern "C" void kernel_launch(void* const* d_in, const int* in_sizes, int n_in,
                              void* d_out, int out_size) {
    const float* x     = (const float*)d_in[0];
    const float* w_off = (const float*)d_in[1];
    const float* b_off = (const float*)d_in[2];
    const float* w     = (const float*)d_in[3];
    const float* gamma = (const float*)d_in[4];
    const float* beta  = (const float*)d_in[5];
    float* out = (float*)d_out;

    cudaFuncSetAttribute(gemm_tf32_kernel<0>,
                         cudaFuncAttributeMaxDynamicSharedMemorySize,
                         SM_FLOATS * 4);
    cudaFuncSetAttribute(gemm_tf32_kernel<1>,
                         cudaFuncAttributeMaxDynamicSharedMemorySize,
                         SM_FLOATS * 4);

    transpose_kernel<<<BN_TOT / 32, dim3(32, 8)>>>(x);
    prep_kernel<<<(96 * CK + 255) / 256, 256>>>(w_off, w);

    dense_gather_kernel<<<BN_TOT, 128>>>();
    gemm_tf32_kernel<0><<<NTILES, 256, SM_FLOATS * 4>>>(b_off, nullptr);

    deform_gather_kernel<<<BN_TOT, 128>>>();
    gemm_tf32_kernel<1><<<NTILES, 256, SM_FLOATS * 4>>>(nullptr, out);

    bn_stats_kernel<<<COUT * 8, 256>>>(out);
    bn_finalize_kernel<<<1, 128>>>(gamma, beta);

    const int TOT4 = BB * COUT * NN / 4;
    bn_apply_kernel<<<(TOT4 + 255) / 256, 256>>>(out);
}